// round 8
// baseline (speedup 1.0000x reference)
#include <cuda_runtime.h>
#include <cuda_bf16.h>
#include <cstdint>

#define SSn 2048
#define DDn 64
#define HHn 16
#define BBn 4
#define L2E 1.4426950408889634f

#define ROWB 144                 // smem row stride (conflict-free ldmatrix)
#define LOFF (128 * ROWB)        // hi->lo plane offset

__device__ float g_inv[BBn * HHn * SSn];

__device__ __forceinline__ uint32_t smem_u32(const void* p) {
    uint32_t a;
    asm("{ .reg .u64 t; cvta.to.shared.u64 t, %1; cvt.u32.u64 %0, t; }" : "=r"(a) : "l"(p));
    return a;
}
__device__ __forceinline__ void mma16816(float* c, const uint32_t* a, const uint32_t* b) {
    asm volatile("mma.sync.aligned.m16n8k16.row.col.f32.bf16.bf16.f32 "
        "{%0,%1,%2,%3}, {%4,%5,%6,%7}, {%8,%9}, {%0,%1,%2,%3};"
        : "+f"(c[0]), "+f"(c[1]), "+f"(c[2]), "+f"(c[3])
        : "r"(a[0]), "r"(a[1]), "r"(a[2]), "r"(a[3]), "r"(b[0]), "r"(b[1]));
}
__device__ __forceinline__ void ldsm4(uint32_t* r, uint32_t a) {
    asm volatile("ldmatrix.sync.aligned.m8n8.x4.shared.b16 {%0,%1,%2,%3}, [%4];"
        : "=r"(r[0]), "=r"(r[1]), "=r"(r[2]), "=r"(r[3]) : "r"(a));
}
__device__ __forceinline__ void ldsm4t(uint32_t* r, uint32_t a) {
    asm volatile("ldmatrix.sync.aligned.m8n8.x4.trans.shared.b16 {%0,%1,%2,%3}, [%4];"
        : "=r"(r[0]), "=r"(r[1]), "=r"(r[2]), "=r"(r[3]) : "r"(a));
}
__device__ __forceinline__ void split2(float x, float y, uint32_t& hp, uint32_t& lp) {
    __nv_bfloat162 h2 = __float22bfloat162_rn(make_float2(x, y));
    float2 hf = __bfloat1622float2(h2);
    __nv_bfloat162 l2 = __float22bfloat162_rn(make_float2(x - hf.x, y - hf.y));
    hp = *reinterpret_cast<uint32_t*>(&h2);
    lp = *reinterpret_cast<uint32_t*>(&l2);
}
__device__ __forceinline__ float ex2(float x) {
    float y; asm("ex2.approx.f32 %0, %1;" : "=f"(y) : "f"(x)); return y;
}

// =====================================================================
// Kernel A: exp((Q/8)K^T + bias + mask) -> Attn (UNNORMALIZED); 1/rowsum -> g_inv
// bias/mask software-prefetched one n-tile ahead.
// =====================================================================
__global__ __launch_bounds__(256) void attn_scores_kernel(
    const float* __restrict__ Q, const float* __restrict__ K,
    const float* __restrict__ Bias, const float* __restrict__ Mask,
    float* __restrict__ Attn)
{
    __shared__ __align__(16) char sK[2 * 128 * ROWB];

    const int tid = threadIdx.x, wid = tid >> 5, lane = tid & 31;
    const int b = blockIdx.x, h = blockIdx.y, qt = blockIdx.z;
    const int bh = b * HHn + h, q0 = qt * 128;
    const int rA = wid * 16 + (lane >> 2);
    const int kA = (lane & 3) * 2;

    uint32_t a_hi[4][4], a_lo[4][4];
    {
        const float* q_r0 = Q + ((size_t)bh * SSn + q0 + rA) * DDn;
        const float* q_r1 = q_r0 + 8 * DDn;
        #pragma unroll
        for (int ks = 0; ks < 4; ++ks) {
            float2 v;
            v = *(const float2*)(q_r0 + ks * 16 + kA);
            split2(v.x * 0.125f, v.y * 0.125f, a_hi[ks][0], a_lo[ks][0]);
            v = *(const float2*)(q_r1 + ks * 16 + kA);
            split2(v.x * 0.125f, v.y * 0.125f, a_hi[ks][1], a_lo[ks][1]);
            v = *(const float2*)(q_r0 + ks * 16 + 8 + kA);
            split2(v.x * 0.125f, v.y * 0.125f, a_hi[ks][2], a_lo[ks][2]);
            v = *(const float2*)(q_r1 + ks * 16 + 8 + kA);
            split2(v.x * 0.125f, v.y * 0.125f, a_hi[ks][3], a_lo[ks][3]);
        }
    }

    const uint32_t sb = smem_u32(sK);
    const float4* Ks = (const float4*)(K + (size_t)bh * SSn * DDn);
    const float* brow0 = Bias + ((size_t)h * SSn + q0 + rA) * SSn;
    const float* brow1 = brow0 + 8 * SSn;
    const float* mrow0 = Mask + ((size_t)b * SSn + q0 + rA) * SSn;
    const float* mrow1 = mrow0 + 8 * SSn;
    float* arow0 = Attn + ((size_t)bh * SSn + q0 + rA) * SSn;
    float* arow1 = arow0 + 8 * SSn;

    const int ln8 = lane & 7, lg = lane >> 3;
    float rs0 = 0.f, rs1 = 0.f;

    // prefetch bias/mask for step 0
    float2 cb0 = *(const float2*)(brow0 + kA);
    float2 cm0 = *(const float2*)(mrow0 + kA);
    float2 cb1 = *(const float2*)(brow1 + kA);
    float2 cm1 = *(const float2*)(mrow1 + kA);

    for (int c = 0; c < 16; ++c) {
        __syncthreads();
        #pragma unroll
        for (int i = 0; i < 8; ++i) {
            int f4 = tid + i * 256;
            int row = f4 >> 4, c4 = f4 & 15;
            float4 v = Ks[c * 2048 + f4];
            uint32_t h0, l0, h1, l1;
            split2(v.x, v.y, h0, l0);
            split2(v.z, v.w, h1, l1);
            char* d = sK + row * ROWB + c4 * 8;
            *(uint2*)d = make_uint2(h0, h1);
            *(uint2*)(d + LOFF) = make_uint2(l0, l1);
        }
        __syncthreads();

        #pragma unroll 2
        for (int nt = 0; nt < 16; ++nt) {
            const uint32_t ba = sb + (uint32_t)((nt * 8 + ln8) * ROWB + lg * 16);
            uint32_t bhf[4][2], blf[4][2], t4[4];
            ldsm4(t4, ba);
            bhf[0][0] = t4[0]; bhf[0][1] = t4[1]; bhf[1][0] = t4[2]; bhf[1][1] = t4[3];
            ldsm4(t4, ba + 64);
            bhf[2][0] = t4[0]; bhf[2][1] = t4[1]; bhf[3][0] = t4[2]; bhf[3][1] = t4[3];
            ldsm4(t4, ba + LOFF);
            blf[0][0] = t4[0]; blf[0][1] = t4[1]; blf[1][0] = t4[2]; blf[1][1] = t4[3];
            ldsm4(t4, ba + LOFF + 64);
            blf[2][0] = t4[0]; blf[2][1] = t4[1]; blf[3][0] = t4[2]; blf[3][1] = t4[3];

            // issue next step's bias/mask loads (consumed next iteration)
            const int s = c * 16 + nt;
            const int coln = (s == 255 ? 2040 : (s + 1) * 8) + kA;
            float2 nb0 = *(const float2*)(brow0 + coln);
            float2 nm0 = *(const float2*)(mrow0 + coln);
            float2 nb1 = *(const float2*)(brow1 + coln);
            float2 nm1 = *(const float2*)(mrow1 + coln);

            float cc[4] = {0.f, 0.f, 0.f, 0.f};
            #pragma unroll
            for (int ks = 0; ks < 4; ++ks) mma16816(cc, a_hi[ks], bhf[ks]);
            #pragma unroll
            for (int ks = 0; ks < 4; ++ks) mma16816(cc, a_hi[ks], blf[ks]);
            #pragma unroll
            for (int ks = 0; ks < 4; ++ks) mma16816(cc, a_lo[ks], bhf[ks]);

            const int col = s * 8 + kA;
            float e0 = ex2((cc[0] + cb0.x + cm0.x) * L2E);
            float e1 = ex2((cc[1] + cb0.y + cm0.y) * L2E);
            float e2 = ex2((cc[2] + cb1.x + cm1.x) * L2E);
            float e3 = ex2((cc[3] + cb1.y + cm1.y) * L2E);
            rs0 += e0 + e1;
            rs1 += e2 + e3;
            *(float2*)(arow0 + col) = make_float2(e0, e1);
            *(float2*)(arow1 + col) = make_float2(e2, e3);

            cb0 = nb0; cm0 = nm0; cb1 = nb1; cm1 = nm1;
        }
    }

    rs0 += __shfl_xor_sync(0xffffffffu, rs0, 1);
    rs0 += __shfl_xor_sync(0xffffffffu, rs0, 2);
    rs1 += __shfl_xor_sync(0xffffffffu, rs1, 1);
    rs1 += __shfl_xor_sync(0xffffffffu, rs1, 2);
    if ((lane & 3) == 0) {
        g_inv[(size_t)bh * SSn + q0 + rA] = 1.f / rs0;
        g_inv[(size_t)bh * SSn + q0 + rA + 8] = 1.f / rs1;
    }
}

// =====================================================================
// Kernel B: normalize Attn in place (required output) + Out = P @ V
// P fragments software-prefetched one k-step ahead; grid = (qt,b,h) for V L2 reuse.
// =====================================================================
__global__ __launch_bounds__(256, 3) void attn_pv_kernel(
    const float* __restrict__ V, float* __restrict__ Attn, float* __restrict__ Out)
{
    __shared__ __align__(16) char sV[2 * 128 * ROWB];

    const int tid = threadIdx.x, wid = tid >> 5, lane = tid & 31;
    const int qt = blockIdx.x, b = blockIdx.y, h = blockIdx.z;
    const int bh = b * HHn + h, q0 = qt * 128;
    const int rA = wid * 16 + (lane >> 2);
    const int kA = (lane & 3) * 2;

    const float inv0 = g_inv[(size_t)bh * SSn + q0 + rA];
    const float inv1 = g_inv[(size_t)bh * SSn + q0 + rA + 8];

    float acc[8][4];
    #pragma unroll
    for (int n = 0; n < 8; ++n)
        #pragma unroll
        for (int j = 0; j < 4; ++j) acc[n][j] = 0.f;

    float* prow0 = Attn + ((size_t)bh * SSn + q0 + rA) * SSn;
    float* prow1 = prow0 + 8 * SSn;
    const float4* Vs = (const float4*)(V + (size_t)bh * SSn * DDn);
    const uint32_t sb = smem_u32(sV);
    const int ln8 = lane & 7, lg1 = (lane >> 3) & 1, lg2 = lane >> 4;

    // prefetch P fragments for kcol = 0
    float2 pf0 = *(float2*)(prow0 + kA);
    float2 pf1 = *(float2*)(prow1 + kA);
    float2 pf2 = *(float2*)(prow0 + 8 + kA);
    float2 pf3 = *(float2*)(prow1 + 8 + kA);

    for (int c = 0; c < 16; ++c) {
        __syncthreads();
        #pragma unroll
        for (int i = 0; i < 8; ++i) {
            int f4 = tid + i * 256;
            int row = f4 >> 4, c4 = f4 & 15;     // row = k within chunk, cols = d
            float4 v = Vs[c * 2048 + f4];
            uint32_t h0, l0, h1, l1;
            split2(v.x, v.y, h0, l0);
            split2(v.z, v.w, h1, l1);
            char* d = sV + row * ROWB + c4 * 8;
            *(uint2*)d = make_uint2(h0, h1);
            *(uint2*)(d + LOFF) = make_uint2(l0, l1);
        }
        __syncthreads();

        #pragma unroll 2
        for (int ks = 0; ks < 8; ++ks) {
            const int kcol = c * 128 + ks * 16;
            const int kn = (kcol < 2032 ? kcol + 16 : 2032);

            // issue next k-step's P loads first (unconditional, clamped)
            float2 np0 = *(float2*)(prow0 + kn + kA);
            float2 np1 = *(float2*)(prow1 + kn + kA);
            float2 np2 = *(float2*)(prow0 + kn + 8 + kA);
            float2 np3 = *(float2*)(prow1 + kn + 8 + kA);

            // normalize current P, write back (required attn output), split to frags
            uint32_t ahi[4], alo[4];
            pf0.x *= inv0; pf0.y *= inv0;
            *(float2*)(prow0 + kcol + kA) = pf0; split2(pf0.x, pf0.y, ahi[0], alo[0]);
            pf1.x *= inv1; pf1.y *= inv1;
            *(float2*)(prow1 + kcol + kA) = pf1; split2(pf1.x, pf1.y, ahi[1], alo[1]);
            pf2.x *= inv0; pf2.y *= inv0;
            *(float2*)(prow0 + kcol + 8 + kA) = pf2; split2(pf2.x, pf2.y, ahi[2], alo[2]);
            pf3.x *= inv1; pf3.y *= inv1;
            *(float2*)(prow1 + kcol + 8 + kA) = pf3; split2(pf3.x, pf3.y, ahi[3], alo[3]);

            const uint32_t ka = sb + (uint32_t)((ks * 16 + lg1 * 8 + ln8) * ROWB + lg2 * 16);
            #pragma unroll
            for (int np = 0; np < 4; ++np) {
                uint32_t t4[4], u4[4];
                ldsm4t(t4, ka + np * 32);          // V hi : d-tiles 2np, 2np+1
                ldsm4t(u4, ka + np * 32 + LOFF);   // V lo
                mma16816(acc[2 * np],     ahi, &t4[0]);
                mma16816(acc[2 * np + 1], ahi, &t4[2]);
                mma16816(acc[2 * np],     ahi, &u4[0]);
                mma16816(acc[2 * np + 1], ahi, &u4[2]);
                mma16816(acc[2 * np],     alo, &t4[0]);
                mma16816(acc[2 * np + 1], alo, &t4[2]);
            }
            pf0 = np0; pf1 = np1; pf2 = np2; pf3 = np3;
        }
    }

    float* orow0 = Out + ((size_t)bh * SSn + q0 + rA) * DDn;
    float* orow1 = orow0 + 8 * DDn;
    #pragma unroll
    for (int nt = 0; nt < 8; ++nt) {
        *(float2*)(orow0 + nt * 8 + kA) = make_float2(acc[nt][0], acc[nt][1]);
        *(float2*)(orow1 + nt * 8 + kA) = make_float2(acc[nt][2], acc[nt][3]);
    }
}

extern "C" void kernel_launch(void* const* d_in, const int* in_sizes, int n_in,
                              void* d_out, int out_size)
{
    const float* Q    = (const float*)d_in[0];
    const float* K    = (const float*)d_in[1];
    const float* V    = (const float*)d_in[2];
    const float* Bias = (const float*)d_in[3];
    const float* Mask = (const float*)d_in[4];
    float* Out  = (float*)d_out;
    float* Attn = Out + (size_t)BBn * HHn * SSn * DDn;

    dim3 gridA(BBn, HHn, SSn / 128);   // b fastest -> bias L2 reuse
    attn_scores_kernel<<<gridA, 256>>>(Q, K, Bias, Mask, Attn);
    dim3 gridB(SSn / 128, BBn, HHn);   // qt fastest -> V L2 reuse within (b,h)
    attn_pv_kernel<<<gridB, 256>>>(V, Attn, Out);
}

// round 9
// speedup vs baseline: 2.0783x; 2.0783x over previous
#include <cuda_runtime.h>
#include <cuda_bf16.h>
#include <cstdint>

#define SSn 2048
#define DDn 64
#define HHn 16
#define BBn 4
#define L2E 1.4426950408889634f

#define ROWB 144                 // smem row stride (conflict-free ldmatrix)
#define LOFF (128 * ROWB)        // hi->lo plane offset (kernel A)

__device__ float g_inv[BBn * HHn * SSn];

__device__ __forceinline__ uint32_t smem_u32(const void* p) {
    uint32_t a;
    asm("{ .reg .u64 t; cvta.to.shared.u64 t, %1; cvt.u32.u64 %0, t; }" : "=r"(a) : "l"(p));
    return a;
}
__device__ __forceinline__ void mma16816(float* c, const uint32_t* a, const uint32_t* b) {
    asm volatile("mma.sync.aligned.m16n8k16.row.col.f32.bf16.bf16.f32 "
        "{%0,%1,%2,%3}, {%4,%5,%6,%7}, {%8,%9}, {%0,%1,%2,%3};"
        : "+f"(c[0]), "+f"(c[1]), "+f"(c[2]), "+f"(c[3])
        : "r"(a[0]), "r"(a[1]), "r"(a[2]), "r"(a[3]), "r"(b[0]), "r"(b[1]));
}
__device__ __forceinline__ void ldsm4(uint32_t* r, uint32_t a) {
    asm volatile("ldmatrix.sync.aligned.m8n8.x4.shared.b16 {%0,%1,%2,%3}, [%4];"
        : "=r"(r[0]), "=r"(r[1]), "=r"(r[2]), "=r"(r[3]) : "r"(a));
}
__device__ __forceinline__ void ldsm4t(uint32_t* r, uint32_t a) {
    asm volatile("ldmatrix.sync.aligned.m8n8.x4.trans.shared.b16 {%0,%1,%2,%3}, [%4];"
        : "=r"(r[0]), "=r"(r[1]), "=r"(r[2]), "=r"(r[3]) : "r"(a));
}
__device__ __forceinline__ void split2(float x, float y, uint32_t& hp, uint32_t& lp) {
    __nv_bfloat162 h2 = __float22bfloat162_rn(make_float2(x, y));
    float2 hf = __bfloat1622float2(h2);
    __nv_bfloat162 l2 = __float22bfloat162_rn(make_float2(x - hf.x, y - hf.y));
    hp = *reinterpret_cast<uint32_t*>(&h2);
    lp = *reinterpret_cast<uint32_t*>(&l2);
}

// =====================================================================
// Kernel A (unchanged round-5 form): exp((Q/8)K^T + bias + mask) -> Attn
// (UNNORMALIZED); 1/rowsum -> g_inv
// =====================================================================
__global__ __launch_bounds__(256) void attn_scores_kernel(
    const float* __restrict__ Q, const float* __restrict__ K,
    const float* __restrict__ Bias, const float* __restrict__ Mask,
    float* __restrict__ Attn)
{
    __shared__ __align__(16) char sK[2 * 128 * ROWB];

    const int tid = threadIdx.x, wid = tid >> 5, lane = tid & 31;
    const int b = blockIdx.x, h = blockIdx.y, qt = blockIdx.z;
    const int bh = b * HHn + h, q0 = qt * 128;
    const int rA = wid * 16 + (lane >> 2);
    const int kA = (lane & 3) * 2;

    uint32_t a_hi[4][4], a_lo[4][4];
    {
        const float* q_r0 = Q + ((size_t)bh * SSn + q0 + rA) * DDn;
        const float* q_r1 = q_r0 + 8 * DDn;
        #pragma unroll
        for (int ks = 0; ks < 4; ++ks) {
            float2 v;
            v = *(const float2*)(q_r0 + ks * 16 + kA);
            split2(v.x * 0.125f, v.y * 0.125f, a_hi[ks][0], a_lo[ks][0]);
            v = *(const float2*)(q_r1 + ks * 16 + kA);
            split2(v.x * 0.125f, v.y * 0.125f, a_hi[ks][1], a_lo[ks][1]);
            v = *(const float2*)(q_r0 + ks * 16 + 8 + kA);
            split2(v.x * 0.125f, v.y * 0.125f, a_hi[ks][2], a_lo[ks][2]);
            v = *(const float2*)(q_r1 + ks * 16 + 8 + kA);
            split2(v.x * 0.125f, v.y * 0.125f, a_hi[ks][3], a_lo[ks][3]);
        }
    }

    const uint32_t sb = smem_u32(sK);
    const float4* Ks = (const float4*)(K + (size_t)bh * SSn * DDn);
    const float* brow0 = Bias + ((size_t)h * SSn + q0 + rA) * SSn;
    const float* brow1 = brow0 + 8 * SSn;
    const float* mrow0 = Mask + ((size_t)b * SSn + q0 + rA) * SSn;
    const float* mrow1 = mrow0 + 8 * SSn;
    float* arow0 = Attn + ((size_t)bh * SSn + q0 + rA) * SSn;
    float* arow1 = arow0 + 8 * SSn;

    const int ln8 = lane & 7, lg = lane >> 3;
    float rs0 = 0.f, rs1 = 0.f;

    for (int c = 0; c < 16; ++c) {
        __syncthreads();
        #pragma unroll
        for (int i = 0; i < 8; ++i) {
            int f4 = tid + i * 256;
            int row = f4 >> 4, c4 = f4 & 15;
            float4 v = Ks[c * 2048 + f4];
            uint32_t h0, l0, h1, l1;
            split2(v.x, v.y, h0, l0);
            split2(v.z, v.w, h1, l1);
            char* d = sK + row * ROWB + c4 * 8;
            *(uint2*)d = make_uint2(h0, h1);
            *(uint2*)(d + LOFF) = make_uint2(l0, l1);
        }
        __syncthreads();

        #pragma unroll 2
        for (int nt = 0; nt < 16; ++nt) {
            const uint32_t ba = sb + (uint32_t)((nt * 8 + ln8) * ROWB + lg * 16);
            uint32_t bhf[4][2], blf[4][2], t4[4];
            ldsm4(t4, ba);
            bhf[0][0] = t4[0]; bhf[0][1] = t4[1]; bhf[1][0] = t4[2]; bhf[1][1] = t4[3];
            ldsm4(t4, ba + 64);
            bhf[2][0] = t4[0]; bhf[2][1] = t4[1]; bhf[3][0] = t4[2]; bhf[3][1] = t4[3];
            ldsm4(t4, ba + LOFF);
            blf[0][0] = t4[0]; blf[0][1] = t4[1]; blf[1][0] = t4[2]; blf[1][1] = t4[3];
            ldsm4(t4, ba + LOFF + 64);
            blf[2][0] = t4[0]; blf[2][1] = t4[1]; blf[3][0] = t4[2]; blf[3][1] = t4[3];

            float cc[4] = {0.f, 0.f, 0.f, 0.f};
            #pragma unroll
            for (int ks = 0; ks < 4; ++ks) mma16816(cc, a_hi[ks], bhf[ks]);
            #pragma unroll
            for (int ks = 0; ks < 4; ++ks) mma16816(cc, a_hi[ks], blf[ks]);
            #pragma unroll
            for (int ks = 0; ks < 4; ++ks) mma16816(cc, a_lo[ks], bhf[ks]);

            const int col = c * 128 + nt * 8 + kA;
            float2 bb0 = *(const float2*)(brow0 + col);
            float2 mm0 = *(const float2*)(mrow0 + col);
            float2 bb1 = *(const float2*)(brow1 + col);
            float2 mm1 = *(const float2*)(mrow1 + col);
            float e0 = exp2f((cc[0] + bb0.x + mm0.x) * L2E);
            float e1 = exp2f((cc[1] + bb0.y + mm0.y) * L2E);
            float e2 = exp2f((cc[2] + bb1.x + mm1.x) * L2E);
            float e3 = exp2f((cc[3] + bb1.y + mm1.y) * L2E);
            rs0 += e0 + e1;
            rs1 += e2 + e3;
            *(float2*)(arow0 + col) = make_float2(e0, e1);
            *(float2*)(arow1 + col) = make_float2(e2, e3);
        }
    }

    rs0 += __shfl_xor_sync(0xffffffffu, rs0, 1);
    rs0 += __shfl_xor_sync(0xffffffffu, rs0, 2);
    rs1 += __shfl_xor_sync(0xffffffffu, rs1, 1);
    rs1 += __shfl_xor_sync(0xffffffffu, rs1, 2);
    if ((lane & 3) == 0) {
        g_inv[(size_t)bh * SSn + q0 + rA] = 1.f / rs0;
        g_inv[(size_t)bh * SSn + q0 + rA + 8] = 1.f / rs1;
    }
}

// =====================================================================
// Kernel B v2: P routed through smem with coalesced float4 I/O.
// Normalizes P during the load (writes the required attn output),
// MMA consumes normalized P via ldmatrix; acc needs no final scaling.
// =====================================================================
#define P_HI 0
#define P_LO 18432                 // 128*144
#define V_HI 36864
#define V_LODELTA 9216             // 64*144
#define S_INV 55296
#define SMEMB_B 55808

__global__ __launch_bounds__(256, 3) void attn_pv_kernel(
    const float* __restrict__ V, float* __restrict__ Attn, float* __restrict__ Out)
{
    extern __shared__ char sm[];
    float* sInv = (float*)(sm + S_INV);

    const int tid = threadIdx.x, wid = tid >> 5, lane = tid & 31;
    const int qt = blockIdx.x, b = blockIdx.y, h = blockIdx.z;
    const int bh = b * HHn + h, q0 = qt * 128;
    const int wq = wid & 7;   // 8 warps... (wid 0..7)
    const int kA = (lane & 3) * 2;
    const int rA = wid * 16 + (lane >> 2);

    if (tid < 128) sInv[tid] = g_inv[(size_t)bh * SSn + q0 + tid];

    float acc[8][4];
    #pragma unroll
    for (int n = 0; n < 8; ++n)
        #pragma unroll
        for (int j = 0; j < 4; ++j) acc[n][j] = 0.f;

    float* Pg = Attn + ((size_t)bh * SSn + q0) * SSn;
    const float4* Vs = (const float4*)(V + (size_t)bh * SSn * DDn);
    const uint32_t sb = smem_u32(sm);
    const int ln8 = lane & 7, lg1 = (lane >> 3) & 1, lg2 = lane >> 4;

    // ldmatrix A-fragment base for P: lanes 0-7 -> rows r0..7, 8-15 -> +8,
    // 16-23 -> k+8 (byte +16), 24-31 -> both
    const uint32_t pbase = sb + P_HI +
        (uint32_t)((wid * 16 + lg1 * 8 + ln8) * ROWB + lg2 * 16);
    const uint32_t vbase = sb + V_HI + (uint32_t)((lg1 * 8 + ln8) * ROWB + lg2 * 16);

    for (int c = 0; c < 32; ++c) {
        __syncthreads();
        // ---- V chunk: 64 k-rows x 64 d, coalesced float4, split hi/lo
        #pragma unroll
        for (int i = 0; i < 4; ++i) {
            int f4 = tid + i * 256;
            int row = f4 >> 4, c4 = f4 & 15;
            float4 v = Vs[c * 1024 + f4];
            uint32_t h0, l0, h1, l1;
            split2(v.x, v.y, h0, l0);
            split2(v.z, v.w, h1, l1);
            char* d = sm + V_HI + row * ROWB + c4 * 8;
            *(uint2*)d = make_uint2(h0, h1);
            *(uint2*)(d + V_LODELTA) = make_uint2(l0, l1);
        }
        // ---- P chunk: 128 q-rows x 64 k; coalesced load, normalize, coalesced
        //      write-back (required attn output), split hi/lo into smem
        #pragma unroll
        for (int i = 0; i < 8; ++i) {
            int f4 = tid + i * 256;
            int row = f4 >> 4, c4 = f4 & 15;
            float4* gp = (float4*)(Pg + (size_t)row * SSn + c * 64) + c4;
            float4 p = *gp;
            const float inv = sInv[row];
            p.x *= inv; p.y *= inv; p.z *= inv; p.w *= inv;
            *gp = p;
            uint32_t h0, l0, h1, l1;
            split2(p.x, p.y, h0, l0);
            split2(p.z, p.w, h1, l1);
            char* d = sm + P_HI + row * ROWB + c4 * 8;
            *(uint2*)d = make_uint2(h0, h1);
            *(uint2*)(d + P_LO) = make_uint2(l0, l1);
        }
        __syncthreads();

        #pragma unroll
        for (int ks = 0; ks < 4; ++ks) {
            uint32_t ahi[4], alo[4];
            ldsm4(ahi, pbase + ks * 32);
            ldsm4(alo, pbase + ks * 32 + P_LO);

            const uint32_t ka = vbase + (uint32_t)(ks * 16 * ROWB);
            #pragma unroll
            for (int np = 0; np < 4; ++np) {
                uint32_t t4[4], u4[4];
                ldsm4t(t4, ka + np * 32);               // V hi : d-tiles 2np, 2np+1
                ldsm4t(u4, ka + np * 32 + V_LODELTA);   // V lo
                mma16816(acc[2 * np],     ahi, &t4[0]);
                mma16816(acc[2 * np + 1], ahi, &t4[2]);
                mma16816(acc[2 * np],     ahi, &u4[0]);
                mma16816(acc[2 * np + 1], ahi, &u4[2]);
                mma16816(acc[2 * np],     alo, &t4[0]);
                mma16816(acc[2 * np + 1], alo, &t4[2]);
            }
        }
    }

    // acc is already normalized (P was normalized before the MMA)
    float* orow0 = Out + ((size_t)bh * SSn + q0 + rA) * DDn;
    float* orow1 = orow0 + 8 * DDn;
    #pragma unroll
    for (int nt = 0; nt < 8; ++nt) {
        *(float2*)(orow0 + nt * 8 + kA) = make_float2(acc[nt][0], acc[nt][1]);
        *(float2*)(orow1 + nt * 8 + kA) = make_float2(acc[nt][2], acc[nt][3]);
    }
    (void)wq;
}

extern "C" void kernel_launch(void* const* d_in, const int* in_sizes, int n_in,
                              void* d_out, int out_size)
{
    const float* Q    = (const float*)d_in[0];
    const float* K    = (const float*)d_in[1];
    const float* V    = (const float*)d_in[2];
    const float* Bias = (const float*)d_in[3];
    const float* Mask = (const float*)d_in[4];
    float* Out  = (float*)d_out;
    float* Attn = Out + (size_t)BBn * HHn * SSn * DDn;

    cudaFuncSetAttribute(attn_pv_kernel,
                         cudaFuncAttributeMaxDynamicSharedMemorySize, SMEMB_B);

    dim3 gridA(BBn, HHn, SSn / 128);   // b fastest -> bias L2 reuse
    attn_scores_kernel<<<gridA, 256>>>(Q, K, Bias, Mask, Attn);
    dim3 gridB(SSn / 128, BBn, HHn);   // qt fastest -> V L2 reuse within (b,h)
    attn_pv_kernel<<<gridB, 256, SMEMB_B>>>(V, Attn, Out);
}